// round 15
// baseline (speedup 1.0000x reference)
#include <cuda_runtime.h>
#include <cstdint>

// yoloLoss: preds (B,14,14,30) f32, truths (B,14,14,30) f32 -> scalar f32.
// 3-stage cp.async ring with wait_group 2 (measured-best slack: group waited
// on was issued two tile-periods earlier) + 3 CTAs/SM concurrency:
// TILE=96 cells, 96 threads, 23040B/stage, 69KB smem, 444 CTAs.
// Last-block finalize epilogue (no memset node).

#define BOXN    2
#define LABELN  20
#define ALL_BOX 10
#define CVALS   30
#define BATCH_INV (1.0f / 4096.0f)

#define TILE         96
#define NTHREADS     96
#define TFLOATS      (TILE * CVALS)        // 2880 floats per tensor
#define TBYTES       (TFLOATS * 4)         // 11520 B
#define CHUNKS       (TBYTES / 16)         // 720 16B chunks per tensor
#define CHUNKS2      (2 * CHUNKS)          // 1440 per tile -> 15 per thread exact
#define STAGE_FLOATS (2 * TFLOATS)         // 5760
#define STAGE_BYTES  (2 * TBYTES)          // 23040
#define NSTAGES      3
#define SMEM_BYTES   (NSTAGES * STAGE_BYTES)   // 69120
#define GRID_CTAS    444                   // 3 per SM

__device__ unsigned int g_done;            // static-init 0
__device__ float        g_partials[GRID_CTAS];

__device__ __forceinline__ void cp16(uint32_t dst, const float* src) {
    asm volatile("cp.async.cg.shared.global [%0], [%1], 16;" :: "r"(dst), "l"(src));
}
__device__ __forceinline__ void cp_commit() {
    asm volatile("cp.async.commit_group;");
}
__device__ __forceinline__ void cp_wait2() {
    asm volatile("cp.async.wait_group 2;");
}
__device__ __forceinline__ void cp_wait0() {
    asm volatile("cp.async.wait_group 0;");
}

__device__ __forceinline__ float cell_loss(const float* __restrict__ P,
                                           const float* __restrict__ T)
{
    const float conf0 = P[4];
    const float conf1 = P[9];
    const float tconf = T[4];

    if (tconf > 0.0f) {
        const float CELLF = 1.0f / 14.0f;
        const float tcx = CELLF * T[0];
        const float tcy = CELLF * T[1];
        const float thw = 0.5f * T[2];
        const float thh = 0.5f * T[3];
        const float t_lt_x = tcx - thw, t_rb_x = tcx + thw;
        const float t_lt_y = tcy - thh, t_rb_y = tcy + thh;
        const float ta = (t_rb_x - t_lt_x) * (t_rb_y - t_lt_y);

        float iou[BOXN];
        #pragma unroll
        for (int b = 0; b < BOXN; b++) {
            const float* pb = P + 5 * b;
            const float pcx = CELLF * pb[0];
            const float pcy = CELLF * pb[1];
            const float phw = 0.5f * pb[2];
            const float phh = 0.5f * pb[3];
            const float p_lt_x = pcx - phw, p_rb_x = pcx + phw;
            const float p_lt_y = pcy - phh, p_rb_y = pcy + phh;
            const float lt_x = fmaxf(p_lt_x, t_lt_x);
            const float lt_y = fmaxf(p_lt_y, t_lt_y);
            const float rb_x = fminf(p_rb_x, t_rb_x);
            const float rb_y = fminf(p_rb_y, t_rb_y);
            const float wx = fmaxf(rb_x - lt_x, 0.0f);
            const float wy = fmaxf(rb_y - lt_y, 0.0f);
            const float inter = wx * wy;
            const float pa = (p_rb_x - p_lt_x) * (p_rb_y - p_lt_y);
            iou[b] = inter / (pa + ta - inter);
        }

        // responsible box: jnp argmax-first-index tie semantics
        int resp;
        if (iou[0] == iou[1]) resp = (conf1 > conf0) ? 1 : 0;
        else                  resp = (iou[1] > iou[0]) ? 1 : 0;
        const float max_iou = fmaxf(iou[0], iou[1]);

        const float* pr = P + 5 * resp;
        const float other_conf = (resp == 0) ? conf1 : conf0;

        const float dx = pr[0] - T[0];
        const float dy = pr[1] - T[1];
        const float dw = sqrtf(pr[2]) - sqrtf(T[2]);
        const float dh = sqrtf(pr[3]) - sqrtf(T[3]);
        float c = 5.0f * (dx * dx + dy * dy + dw * dw + dh * dh);

        const float dc = pr[4] - max_iou;
        c += dc * dc;
        c += 0.5f * other_conf * other_conf;

        #pragma unroll
        for (int k = 0; k < LABELN; k++) {
            const float d = P[ALL_BOX + k] - T[ALL_BOX + k];
            c += d * d;
        }
        return c;
    } else {
        return 0.5f * (conf0 * conf0 + conf1 * conf1);
    }
}

__device__ __forceinline__ void prefetch_tile(int tile, int stage,
                                              const float* __restrict__ preds,
                                              const float* __restrict__ truths,
                                              uint32_t sbase, int tid)
{
    const long long base = (long long)tile * TFLOATS;
    const float* gp = preds + base;
    const float* gt = truths + base;
    const uint32_t s = sbase + (uint32_t)stage * STAGE_BYTES;
    // 1440 16B chunks / 96 threads = 15 per thread, exact
    #pragma unroll
    for (int k = 0; k < 15; k++) {
        const int idx = k * NTHREADS + tid;      // 0..1439
        if (idx < CHUNKS) cp16(s + idx * 16, gp + idx * 4);
        else              cp16(s + idx * 16, gt + (idx - CHUNKS) * 4);
    }
}

extern __shared__ float sdata[];

__global__ void __launch_bounds__(NTHREADS)
yolo_loss_kernel(const float* __restrict__ preds,
                 const float* __restrict__ truths,
                 float* __restrict__ out,
                 int n_tiles, int n_cells, float batch_inv)
{
    __shared__ float warp_sums[NTHREADS / 32];
    __shared__ int   s_last;

    const int tid = threadIdx.x;
    const uint32_t sbase = (uint32_t)__cvta_generic_to_shared(sdata);
    const int g = gridDim.x;

    float acc = 0.0f;

    // prologue: prefetch two tiles ahead (stages 0 and 1)
    const int t0 = blockIdx.x;
    if (t0 < n_tiles)
        prefetch_tile(t0, 0, preds, truths, sbase, tid);
    cp_commit();
    if (t0 + g < n_tiles)
        prefetch_tile(t0 + g, 1, preds, truths, sbase, tid);
    cp_commit();

    int stage = 0;
    for (int t = t0; t < n_tiles; t += g) {
        // refill the stage freed last iteration with tile t+2g
        const int t2 = t + 2 * g;
        const int s2 = (stage + 2) % NSTAGES;
        if (t2 < n_tiles)
            prefetch_tile(t2, s2, preds, truths, sbase, tid);
        cp_commit();           // one group per iteration keeps FIFO accounting fixed
        cp_wait2();            // oldest group (stage t) was issued 2 iters ago
        __syncthreads();       // staged tile visible to all threads

        const float* P = sdata + stage * STAGE_FLOATS + tid * CVALS;
        const float* T = P + TFLOATS;
        acc += cell_loss(P, T);

        __syncthreads();       // stage consumed; refillable next iteration
        stage = (stage + 1 == NSTAGES) ? 0 : stage + 1;
    }
    cp_wait0();                // drain trailing groups

    // remainder (802816 - 8362*96 = 64 cells): CTA 0, direct loads
    if (blockIdx.x == 0) {
        const int cell = n_tiles * TILE + tid;
        if (cell < n_cells)
            acc += cell_loss(preds + (long long)cell * CVALS,
                             truths + (long long)cell * CVALS);
    }

    // block reduce -> per-CTA partial
    #pragma unroll
    for (int off = 16; off > 0; off >>= 1)
        acc += __shfl_down_sync(0xFFFFFFFFu, acc, off);
    if ((tid & 31) == 0) warp_sums[tid >> 5] = acc;
    __syncthreads();

    if (tid == 0) {
        float s = 0.0f;
        #pragma unroll
        for (int w = 0; w < NTHREADS / 32; w++) s += warp_sums[w];
        g_partials[blockIdx.x] = s;
        __threadfence();
        const unsigned v = atomicAdd(&g_done, 1u);
        s_last = (v == gridDim.x - 1) ? 1 : 0;
    }
    __syncthreads();

    // last CTA: final reduce, write out, reset counter for next graph replay
    if (s_last) {
        float tot = 0.0f;
        for (int i = tid; i < GRID_CTAS; i += NTHREADS) tot += g_partials[i];
        #pragma unroll
        for (int off = 16; off > 0; off >>= 1)
            tot += __shfl_down_sync(0xFFFFFFFFu, tot, off);
        if ((tid & 31) == 0) warp_sums[tid >> 5] = tot;
        __syncthreads();
        if (tid == 0) {
            float s = 0.0f;
            #pragma unroll
            for (int w = 0; w < NTHREADS / 32; w++) s += warp_sums[w];
            out[0] = s * batch_inv;
            g_done = 0u;
        }
    }
}

extern "C" void kernel_launch(void* const* d_in, const int* in_sizes, int n_in,
                              void* d_out, int out_size)
{
    const float* preds  = (const float*)d_in[0];
    const float* truths = (const float*)d_in[1];
    float* out = (float*)d_out;

    const int n_cells = in_sizes[0] / CVALS;     // 802816
    const int n_tiles = n_cells / TILE;          // 8362 (remainder 64 cells)

    cudaFuncSetAttribute(yolo_loss_kernel,
                         cudaFuncAttributeMaxDynamicSharedMemorySize, SMEM_BYTES);

    yolo_loss_kernel<<<GRID_CTAS, NTHREADS, SMEM_BYTES, 0>>>(preds, truths, out,
                                                             n_tiles, n_cells,
                                                             BATCH_INV);
}

// round 16
// speedup vs baseline: 1.1813x; 1.1813x over previous
#include <cuda_runtime.h>
#include <cstdint>

// yoloLoss: preds (B,14,14,30) f32, truths (B,14,14,30) f32 -> scalar f32.
// FINAL (= R13 measured optimum): 3-stage cp.async ring, wait_group 2 (the
// group being waited on was issued two tile-periods earlier, so the wait
// retires immediately and prefetch bursts fully overlap compute).
// 296 CTAs x 128 thr (2/SM, 92KB smem), static interleave, last-block
// finalize epilogue (no memset node). Measured: 71.4% DRAM, 34.8us kernel.

#define BOXN    2
#define LABELN  20
#define ALL_BOX 10
#define CVALS   30
#define BATCH_INV (1.0f / 4096.0f)

#define TILE         128
#define TFLOATS      (TILE * CVALS)        // 3840 floats per tensor
#define TBYTES       (TFLOATS * 4)         // 15360 B
#define CHUNKS       (TBYTES / 16)         // 960 16B chunks per tensor
#define STAGE_FLOATS (2 * TFLOATS)         // 7680
#define STAGE_BYTES  (2 * TBYTES)          // 30720
#define NSTAGES      3
#define SMEM_BYTES   (NSTAGES * STAGE_BYTES)   // 92160
#define NTHREADS     128
#define GRID_CTAS    296                   // 2 per SM

__device__ unsigned int g_done;            // static-init 0
__device__ float        g_partials[GRID_CTAS];

__device__ __forceinline__ void cp16(uint32_t dst, const float* src) {
    asm volatile("cp.async.cg.shared.global [%0], [%1], 16;" :: "r"(dst), "l"(src));
}
__device__ __forceinline__ void cp_commit() {
    asm volatile("cp.async.commit_group;");
}
__device__ __forceinline__ void cp_wait2() {
    asm volatile("cp.async.wait_group 2;");
}
__device__ __forceinline__ void cp_wait0() {
    asm volatile("cp.async.wait_group 0;");
}

__device__ __forceinline__ float cell_loss(const float* __restrict__ P,
                                           const float* __restrict__ T)
{
    const float conf0 = P[4];
    const float conf1 = P[9];
    const float tconf = T[4];

    if (tconf > 0.0f) {
        const float CELLF = 1.0f / 14.0f;
        const float tcx = CELLF * T[0];
        const float tcy = CELLF * T[1];
        const float thw = 0.5f * T[2];
        const float thh = 0.5f * T[3];
        const float t_lt_x = tcx - thw, t_rb_x = tcx + thw;
        const float t_lt_y = tcy - thh, t_rb_y = tcy + thh;
        const float ta = (t_rb_x - t_lt_x) * (t_rb_y - t_lt_y);

        float iou[BOXN];
        #pragma unroll
        for (int b = 0; b < BOXN; b++) {
            const float* pb = P + 5 * b;
            const float pcx = CELLF * pb[0];
            const float pcy = CELLF * pb[1];
            const float phw = 0.5f * pb[2];
            const float phh = 0.5f * pb[3];
            const float p_lt_x = pcx - phw, p_rb_x = pcx + phw;
            const float p_lt_y = pcy - phh, p_rb_y = pcy + phh;
            const float lt_x = fmaxf(p_lt_x, t_lt_x);
            const float lt_y = fmaxf(p_lt_y, t_lt_y);
            const float rb_x = fminf(p_rb_x, t_rb_x);
            const float rb_y = fminf(p_rb_y, t_rb_y);
            const float wx = fmaxf(rb_x - lt_x, 0.0f);
            const float wy = fmaxf(rb_y - lt_y, 0.0f);
            const float inter = wx * wy;
            const float pa = (p_rb_x - p_lt_x) * (p_rb_y - p_lt_y);
            iou[b] = inter / (pa + ta - inter);
        }

        // responsible box: jnp argmax-first-index tie semantics
        int resp;
        if (iou[0] == iou[1]) resp = (conf1 > conf0) ? 1 : 0;
        else                  resp = (iou[1] > iou[0]) ? 1 : 0;
        const float max_iou = fmaxf(iou[0], iou[1]);

        const float* pr = P + 5 * resp;
        const float other_conf = (resp == 0) ? conf1 : conf0;

        const float dx = pr[0] - T[0];
        const float dy = pr[1] - T[1];
        const float dw = sqrtf(pr[2]) - sqrtf(T[2]);
        const float dh = sqrtf(pr[3]) - sqrtf(T[3]);
        float c = 5.0f * (dx * dx + dy * dy + dw * dw + dh * dh);

        const float dc = pr[4] - max_iou;
        c += dc * dc;
        c += 0.5f * other_conf * other_conf;

        #pragma unroll
        for (int k = 0; k < LABELN; k++) {
            const float d = P[ALL_BOX + k] - T[ALL_BOX + k];
            c += d * d;
        }
        return c;
    } else {
        return 0.5f * (conf0 * conf0 + conf1 * conf1);
    }
}

__device__ __forceinline__ void prefetch_tile(int tile, int stage,
                                              const float* __restrict__ preds,
                                              const float* __restrict__ truths,
                                              uint32_t sbase, int tid)
{
    const long long base = (long long)tile * TFLOATS;
    const float* gp = preds + base;
    const float* gt = truths + base;
    const uint32_t s = sbase + (uint32_t)stage * STAGE_BYTES;
    // 1920 16B chunks / 128 threads = 15 per thread
    #pragma unroll
    for (int k = 0; k < 15; k++) {
        const int idx = k * NTHREADS + tid;      // 0..1919
        if (idx < CHUNKS) cp16(s + idx * 16, gp + idx * 4);
        else              cp16(s + idx * 16, gt + (idx - CHUNKS) * 4);
    }
}

extern __shared__ float sdata[];

__global__ void __launch_bounds__(NTHREADS)
yolo_loss_kernel(const float* __restrict__ preds,
                 const float* __restrict__ truths,
                 float* __restrict__ out,
                 int n_tiles, int n_cells, float batch_inv)
{
    __shared__ float warp_sums[NTHREADS / 32];
    __shared__ int   s_last;

    const int tid = threadIdx.x;
    const uint32_t sbase = (uint32_t)__cvta_generic_to_shared(sdata);
    const int g = gridDim.x;

    float acc = 0.0f;

    // prologue: prefetch two tiles ahead (stages 0 and 1)
    const int t0 = blockIdx.x;
    if (t0 < n_tiles)
        prefetch_tile(t0, 0, preds, truths, sbase, tid);
    cp_commit();
    if (t0 + g < n_tiles)
        prefetch_tile(t0 + g, 1, preds, truths, sbase, tid);
    cp_commit();

    int stage = 0;
    for (int t = t0; t < n_tiles; t += g) {
        // refill the stage freed last iteration with tile t+2g
        const int t2 = t + 2 * g;
        const int s2 = (stage + 2) % NSTAGES;
        if (t2 < n_tiles)
            prefetch_tile(t2, s2, preds, truths, sbase, tid);
        cp_commit();           // one group per iteration keeps FIFO accounting fixed
        cp_wait2();            // oldest group (stage t) was issued 2 iters ago
        __syncthreads();       // staged tile visible to all threads

        const float* P = sdata + stage * STAGE_FLOATS + tid * CVALS;
        const float* T = P + TFLOATS;
        acc += cell_loss(P, T);

        __syncthreads();       // stage consumed; refillable next iteration
        stage = (stage + 1 == NSTAGES) ? 0 : stage + 1;
    }
    cp_wait0();                // drain trailing groups

    // generic remainder (zero for this shape: 802816 = 6272*128): CTA 0
    if (blockIdx.x == 0) {
        const int cell = n_tiles * TILE + tid;
        if (cell < n_cells)
            acc += cell_loss(preds + (long long)cell * CVALS,
                             truths + (long long)cell * CVALS);
    }

    // block reduce -> per-CTA partial
    #pragma unroll
    for (int off = 16; off > 0; off >>= 1)
        acc += __shfl_down_sync(0xFFFFFFFFu, acc, off);
    if ((tid & 31) == 0) warp_sums[tid >> 5] = acc;
    __syncthreads();

    if (tid == 0) {
        float s = 0.0f;
        #pragma unroll
        for (int w = 0; w < NTHREADS / 32; w++) s += warp_sums[w];
        g_partials[blockIdx.x] = s;
        __threadfence();
        const unsigned v = atomicAdd(&g_done, 1u);
        s_last = (v == gridDim.x - 1) ? 1 : 0;
    }
    __syncthreads();

    // last CTA: final reduce, write out, reset counter for next graph replay
    if (s_last) {
        float tot = 0.0f;
        for (int i = tid; i < GRID_CTAS; i += NTHREADS) tot += g_partials[i];
        #pragma unroll
        for (int off = 16; off > 0; off >>= 1)
            tot += __shfl_down_sync(0xFFFFFFFFu, tot, off);
        if ((tid & 31) == 0) warp_sums[tid >> 5] = tot;
        __syncthreads();
        if (tid == 0) {
            float s = 0.0f;
            #pragma unroll
            for (int w = 0; w < NTHREADS / 32; w++) s += warp_sums[w];
            out[0] = s * batch_inv;
            g_done = 0u;
        }
    }
}

extern "C" void kernel_launch(void* const* d_in, const int* in_sizes, int n_in,
                              void* d_out, int out_size)
{
    const float* preds  = (const float*)d_in[0];
    const float* truths = (const float*)d_in[1];
    float* out = (float*)d_out;

    const int n_cells = in_sizes[0] / CVALS;     // 802816
    const int n_tiles = n_cells / TILE;          // 6272

    cudaFuncSetAttribute(yolo_loss_kernel,
                         cudaFuncAttributeMaxDynamicSharedMemorySize, SMEM_BYTES);

    yolo_loss_kernel<<<GRID_CTAS, NTHREADS, SMEM_BYTES, 0>>>(preds, truths, out,
                                                             n_tiles, n_cells,
                                                             BATCH_INV);
}